// round 7
// baseline (speedup 1.0000x reference)
#include <cuda_runtime.h>

// SpinorBilinears: psi [B=8, N=65536, S=4] f32, gamma [C=8, 4, 4] f32.
// Outputs flat: K0 [BN] | K1 [BN,8,8] | K2 [BN,8,8]
//
// Algebra: W[c][d] = p^T gamma_c gamma_d p = <Gsym_cd[10], outer10(p)>
//   K1 = 0.5(W - W^T), K2 = 0.5(W + W^T)   (0.5 folded into coeffs)
// Prep kernel packs Gsym (64 pairs x 10 coeffs, padded to 12) once.
// Main kernel: 8 threads/token; thread c computes row w[d]=0.5*W[c][d],
// obtains wt[d]=0.5*W[d][c] via in-register 8x8 butterfly transpose (SHFL),
// stores rows directly (coalesced). No smem exchange, no hot-path barriers.

#define TPB 256

__device__ float g_coef[768];   // [64 pairs][12], row index = d*8+c for pair (c,d)

__global__ void spinor_prep_kernel(const float* __restrict__ gamma) {
    const int tid = threadIdx.x;          // 0..63
    const int c = tid >> 3, d = tid & 7;
    const float* gc = gamma + c * 16;
    const float* gd = gamma + d * 16;

    float G[4][4];
#pragma unroll
    for (int i = 0; i < 4; i++)
#pragma unroll
        for (int j = 0; j < 4; j++) {
            float s = 0.f;
#pragma unroll
            for (int k = 0; k < 4; k++) s = fmaf(gc[i * 4 + k], gd[k * 4 + j], s);
            G[i][j] = s;
        }

    float cf[12];
    cf[0] = G[0][0];            cf[1] = G[0][1] + G[1][0];
    cf[2] = G[0][2] + G[2][0];  cf[3] = G[0][3] + G[3][0];
    cf[4] = G[1][1];            cf[5] = G[1][2] + G[2][1];
    cf[6] = G[1][3] + G[3][1];  cf[7] = G[2][2];
    cf[8] = G[2][3] + G[3][2];  cf[9] = G[3][3];
    cf[10] = 0.f; cf[11] = 0.f;

    float* dst = &g_coef[(d * 8 + c) * 12];
#pragma unroll
    for (int k = 0; k < 12; k++) dst[k] = 0.5f * cf[k];
}

__global__ __launch_bounds__(TPB) void spinor_main_kernel(
    const float4* __restrict__ psi4,
    float* __restrict__ out,
    int BN)
{
    __shared__ float sc[768];   // row stride 12 floats: 8 lanes' rows span all 32 banks

    const int tid = threadIdx.x;
    if (tid < 192)
        reinterpret_cast<float4*>(sc)[tid] =
            reinterpret_cast<const float4*>(g_coef)[tid];
    __syncthreads();

    const int gth = blockIdx.x * TPB + tid;
    const int t   = gth >> 3;           // token
    const int c   = tid & 7;            // row index 0..7

    const float4 p = psi4[t];           // 8 lanes/token share one 16B load (broadcast)

    float o[10];
    o[0] = p.x * p.x; o[1] = p.x * p.y; o[2] = p.x * p.z; o[3] = p.x * p.w;
    o[4] = p.y * p.y; o[5] = p.y * p.z; o[6] = p.y * p.w;
    o[7] = p.z * p.z; o[8] = p.z * p.w; o[9] = p.w * p.w;

    if (c == 0) out[t] = o[0] + o[4] + o[7] + o[9];   // K0

    // w[d] = 0.5 * W[c][d]
    float w[8];
#pragma unroll
    for (int d = 0; d < 8; d++) {
        const float4* cf4 = reinterpret_cast<const float4*>(&sc[(d * 8 + c) * 12]);
        const float4 a = cf4[0], b = cf4[1], e = cf4[2];
        float acc;
        acc = a.x * o[0];
        acc = fmaf(a.y, o[1], acc); acc = fmaf(a.z, o[2], acc);
        acc = fmaf(a.w, o[3], acc); acc = fmaf(b.x, o[4], acc);
        acc = fmaf(b.y, o[5], acc); acc = fmaf(b.z, o[6], acc);
        acc = fmaf(b.w, o[7], acc); acc = fmaf(e.x, o[8], acc);
        acc = fmaf(e.y, o[9], acc);
        w[d] = acc;
    }

    // wt[d] = 0.5 * W[d][c] via 8x8 in-register butterfly transpose (8-lane groups)
    float wt[8];
#pragma unroll
    for (int r = 0; r < 8; r++) wt[r] = w[r];
#pragma unroll
    for (int m = 1; m < 8; m <<= 1) {
        float nt[8];
#pragma unroll
        for (int r = 0; r < 8; r++) {
            const float other = __shfl_xor_sync(0xFFFFFFFFu, wt[r ^ m], m);
            nt[r] = ((c ^ r) & m) ? other : wt[r];
        }
#pragma unroll
        for (int r = 0; r < 8; r++) wt[r] = nt[r];
    }

    // direct coalesced stores: thread owns 32 B at t*64 + c*8 per tensor
    const size_t bn   = (size_t)BN;
    const size_t base = (size_t)t * 64 + (size_t)c * 8;

    float4* __restrict__ o1 = reinterpret_cast<float4*>(out + bn + base);
    o1[0] = make_float4(w[0] - wt[0], w[1] - wt[1], w[2] - wt[2], w[3] - wt[3]);
    o1[1] = make_float4(w[4] - wt[4], w[5] - wt[5], w[6] - wt[6], w[7] - wt[7]);

    float4* __restrict__ o2 = reinterpret_cast<float4*>(out + bn + bn * 64 + base);
    o2[0] = make_float4(w[0] + wt[0], w[1] + wt[1], w[2] + wt[2], w[3] + wt[3]);
    o2[1] = make_float4(w[4] + wt[4], w[5] + wt[5], w[6] + wt[6], w[7] + wt[7]);
}

extern "C" void kernel_launch(void* const* d_in, const int* in_sizes, int n_in,
                              void* d_out, int out_size) {
    const float4* psi4  = (const float4*)d_in[0];   // [B, N, 4] f32
    const float*  gamma = (const float*)d_in[1];    // [8, 4, 4] f32
    float* out = (float*)d_out;

    const int BN = in_sizes[0] / 4;                 // 524288 tokens

    spinor_prep_kernel<<<1, 64>>>(gamma);
    spinor_main_kernel<<<(BN * 8) / TPB, TPB>>>(psi4, out, BN);
}

// round 8
// speedup vs baseline: 1.4891x; 1.4891x over previous
#include <cuda_runtime.h>

// SpinorBilinears: psi [B=8, N=65536, S=4] f32, gamma [C=8, 4, 4] f32.
// Outputs flat: K0 [BN] | K1 [BN,8,8] | K2 [BN,8,8]
//   u_c = gamma_c^T (0.5 p),  v_c = gamma_c p     (0.5 folded into u)
//   K1[c][d] = u_c.v_d - u_d.v_c,   K2[c][d] = u_c.v_d + u_d.v_c
//
// One thread per token. gamma in __constant__ (LDC, off the MIO pipe).
// Warp-private 8KB swizzled staging + __syncwarp only -> coalesced STG.128,
// no block barriers, warps stream independently.

#define TPB 128

__constant__ float4 cgam[32];   // 8 matrices x 4 rows

__device__ __forceinline__ float dot4f(float4 a, float4 b) {
    return fmaf(a.x, b.x, fmaf(a.y, b.y, fmaf(a.z, b.z, a.w * b.w)));
}

__device__ __forceinline__ int swz(int e4, int l) {     // float4-index swizzle
    return (e4 & 8) | ((e4 & 7) ^ (l & 7));
}

__global__ __launch_bounds__(TPB, 5) void spinor_main_kernel(
    const float4* __restrict__ psi4,
    float* __restrict__ out,
    int BN)
{
    __shared__ float4 stage4[4][512];    // 8 KB per warp

    const int tid  = threadIdx.x;
    const int warp = tid >> 5;
    const int l    = tid & 31;
    const int t    = blockIdx.x * TPB + tid;    // token (grid exact)

    const float4 p = psi4[t];

    // K0 (coalesced STG.32)
    out[t] = dot4f(p, p);

    // u_c = gamma_c^T (0.5p) ; v_c = gamma_c p   (gamma via constant port)
    const float4 ph = make_float4(0.5f * p.x, 0.5f * p.y, 0.5f * p.z, 0.5f * p.w);
    float4 u[8], v[8];
#pragma unroll
    for (int c = 0; c < 8; c++) {
        const float4 r0 = cgam[c * 4 + 0];
        const float4 r1 = cgam[c * 4 + 1];
        const float4 r2 = cgam[c * 4 + 2];
        const float4 r3 = cgam[c * 4 + 3];
        v[c].x = dot4f(r0, p);
        v[c].y = dot4f(r1, p);
        v[c].z = dot4f(r2, p);
        v[c].w = dot4f(r3, p);
        u[c].x = fmaf(r0.x, ph.x, fmaf(r1.x, ph.y, fmaf(r2.x, ph.z, r3.x * ph.w)));
        u[c].y = fmaf(r0.y, ph.x, fmaf(r1.y, ph.y, fmaf(r2.y, ph.z, r3.y * ph.w)));
        u[c].z = fmaf(r0.z, ph.x, fmaf(r1.z, ph.y, fmaf(r2.z, ph.z, r3.z * ph.w)));
        u[c].w = fmaf(r0.w, ph.x, fmaf(r1.w, ph.y, fmaf(r2.w, ph.z, r3.w * ph.w)));
    }

    const size_t  bn = (size_t)BN;
    const int     t0 = blockIdx.x * TPB + warp * 32;   // warp's first token
    float4* __restrict__ k1dst = reinterpret_cast<float4*>(out + bn) + (size_t)t0 * 16;
    float4* __restrict__ k2dst = reinterpret_cast<float4*>(out + bn + bn * 64) + (size_t)t0 * 16;

    // ================= K1 =================
#pragma unroll
    for (int c = 0; c < 8; c++) {
#pragma unroll
        for (int d4 = 0; d4 < 2; d4++) {
            const int d = d4 * 4;
            float4 r;
            r.x = dot4f(u[c], v[d + 0]) - dot4f(u[d + 0], v[c]);
            r.y = dot4f(u[c], v[d + 1]) - dot4f(u[d + 1], v[c]);
            r.z = dot4f(u[c], v[d + 2]) - dot4f(u[d + 2], v[c]);
            r.w = dot4f(u[c], v[d + 3]) - dot4f(u[d + 3], v[c]);
            stage4[warp][l * 16 + swz(c * 2 + d4, l)] = r;
        }
    }
    __syncwarp();
#pragma unroll
    for (int i = 0; i < 16; i++) {
        const int f4  = i * 32 + l;
        const int tok = f4 >> 4;
        const int e4  = f4 & 15;
        k1dst[f4] = stage4[warp][tok * 16 + swz(e4, tok)];
    }
    __syncwarp();

    // ================= K2 =================
#pragma unroll
    for (int c = 0; c < 8; c++) {
#pragma unroll
        for (int d4 = 0; d4 < 2; d4++) {
            const int d = d4 * 4;
            float4 r;
            r.x = dot4f(u[c], v[d + 0]) + dot4f(u[d + 0], v[c]);
            r.y = dot4f(u[c], v[d + 1]) + dot4f(u[d + 1], v[c]);
            r.z = dot4f(u[c], v[d + 2]) + dot4f(u[d + 2], v[c]);
            r.w = dot4f(u[c], v[d + 3]) + dot4f(u[d + 3], v[c]);
            stage4[warp][l * 16 + swz(c * 2 + d4, l)] = r;
        }
    }
    __syncwarp();
#pragma unroll
    for (int i = 0; i < 16; i++) {
        const int f4  = i * 32 + l;
        const int tok = f4 >> 4;
        const int e4  = f4 & 15;
        k2dst[f4] = stage4[warp][tok * 16 + swz(e4, tok)];
    }
}

extern "C" void kernel_launch(void* const* d_in, const int* in_sizes, int n_in,
                              void* d_out, int out_size) {
    const float4* psi4 = (const float4*)d_in[0];   // [B, N, 4] f32
    float* out = (float*)d_out;

    const int BN = in_sizes[0] / 4;                // 524288 tokens

    // gamma (512 B) -> constant bank, async D2D (graph-capturable)
    cudaMemcpyToSymbolAsync(cgam, d_in[1], 32 * sizeof(float4), 0,
                            cudaMemcpyDeviceToDevice, 0);

    spinor_main_kernel<<<BN / TPB, TPB>>>(psi4, out, BN);
}